// round 6
// baseline (speedup 1.0000x reference)
#include <cuda_runtime.h>

// ---------------------------------------------------------------------------
// HydraAttention: qkv = x@Wqkv+b; q,k cosine-normalized over D; kv = sum_T k*v;
// out = (q * kv) @ Wout + bout.   B=4, T=4096, D=1024.
// Baseline fp32 SIMT implementation:
//   k1: SGEMM 16384x3072x1024  -> g_qkv
//   k2: per-row inv-norms of q,k
//   k3: two-stage deterministic pool kv[b,d] = sum_t khat*v
//   k4: SGEMM 16384x1024x1024 with A-load fused scaling q*invq*kv
// ---------------------------------------------------------------------------

#define BATCH 4
#define SEQT  4096
#define DMODEL 1024
#define MROWS (BATCH * SEQT)          // 16384
#define N3D   (3 * DMODEL)            // 3072
#define TCHUNKS 32                    // T split for the pool reduction
#define TPER    (SEQT / TCHUNKS)      // 128

// Scratch (device globals — allocation-free per harness rules)
__device__ float g_qkv[(size_t)MROWS * N3D];     // ~192 MB
__device__ float g_invq[MROWS];
__device__ float g_invk[MROWS];
__device__ float g_kvpart[TCHUNKS * BATCH * DMODEL];
__device__ float g_kv[BATCH * DMODEL];

// ---------------------------------------------------------------------------
// Tiled SGEMM: C[M,N] = A[M,K] @ B[K,N] + bias[N]
// Tile 128x128x8, 256 threads, 8x8 accumulators per thread.
// FUSED: A element (m,k) is scaled by invq[m] * kvp[batch(m)*D + k]
//        (implements hid = q_hat * kv without materializing it).
// ---------------------------------------------------------------------------
template <bool FUSED>
__global__ __launch_bounds__(256, 2)
void sgemm_kernel(const float* __restrict__ A, int lda,
                  const float* __restrict__ B, int ldb,
                  const float* __restrict__ bias,
                  float* __restrict__ C, int ldc,
                  int K,
                  const float* __restrict__ invq,
                  const float* __restrict__ kvp)
{
    __shared__ float As[8][128];
    __shared__ float Bs[8][128];

    const int tid = threadIdx.x;
    const int m0  = blockIdx.y * 128;
    const int n0  = blockIdx.x * 128;

    // A tile loader: 128 rows x 8 cols, one float4 per thread
    const int arow = tid >> 1;             // 0..127
    const int acol = (tid & 1) << 2;       // 0 or 4
    // B tile loader: 8 rows x 128 cols, one float4 per thread
    const int brow = tid >> 5;             // 0..7
    const int bcol = (tid & 31) << 2;      // 0..124

    const int tx = tid & 15;
    const int ty = tid >> 4;

    float acc[8][8];
    #pragma unroll
    for (int i = 0; i < 8; ++i)
        #pragma unroll
        for (int j = 0; j < 8; ++j) acc[i][j] = 0.f;

    const float* Aptr = A + (size_t)(m0 + arow) * lda + acol;
    const float* Bptr = B + (size_t)brow * ldb + n0 + bcol;

    float invq_r = 0.f;
    int   kvbase = 0;
    if (FUSED) {
        invq_r = invq[m0 + arow];
        kvbase = ((m0 + arow) >> 12) << 10;   // batch(m) * DMODEL (T=4096)
    }

    for (int k0 = 0; k0 < K; k0 += 8) {
        float4 av = *reinterpret_cast<const float4*>(Aptr + k0);
        float4 bv = *reinterpret_cast<const float4*>(Bptr + (size_t)k0 * ldb);
        if (FUSED) {
            const int kc = kvbase + k0 + acol;
            av.x *= invq_r * kvp[kc + 0];
            av.y *= invq_r * kvp[kc + 1];
            av.z *= invq_r * kvp[kc + 2];
            av.w *= invq_r * kvp[kc + 3];
        }
        __syncthreads();
        As[acol + 0][arow] = av.x;
        As[acol + 1][arow] = av.y;
        As[acol + 2][arow] = av.z;
        As[acol + 3][arow] = av.w;
        *reinterpret_cast<float4*>(&Bs[brow][bcol]) = bv;
        __syncthreads();

        #pragma unroll
        for (int kk = 0; kk < 8; ++kk) {
            float4 a0 = *reinterpret_cast<const float4*>(&As[kk][ty * 8]);
            float4 a1 = *reinterpret_cast<const float4*>(&As[kk][ty * 8 + 4]);
            float4 b0 = *reinterpret_cast<const float4*>(&Bs[kk][tx * 8]);
            float4 b1 = *reinterpret_cast<const float4*>(&Bs[kk][tx * 8 + 4]);
            float a[8] = {a0.x, a0.y, a0.z, a0.w, a1.x, a1.y, a1.z, a1.w};
            float b[8] = {b0.x, b0.y, b0.z, b0.w, b1.x, b1.y, b1.z, b1.w};
            #pragma unroll
            for (int i = 0; i < 8; ++i)
                #pragma unroll
                for (int j = 0; j < 8; ++j)
                    acc[i][j] += a[i] * b[j];
        }
    }

    // Epilogue: add bias, vectorized store
    float4 bia0 = *reinterpret_cast<const float4*>(bias + n0 + tx * 8);
    float4 bia1 = *reinterpret_cast<const float4*>(bias + n0 + tx * 8 + 4);
    #pragma unroll
    for (int i = 0; i < 8; ++i) {
        float* crow = C + (size_t)(m0 + ty * 8 + i) * ldc + n0 + tx * 8;
        float4 v0, v1;
        v0.x = acc[i][0] + bia0.x; v0.y = acc[i][1] + bia0.y;
        v0.z = acc[i][2] + bia0.z; v0.w = acc[i][3] + bia0.w;
        v1.x = acc[i][4] + bia1.x; v1.y = acc[i][5] + bia1.y;
        v1.z = acc[i][6] + bia1.z; v1.w = acc[i][7] + bia1.w;
        *reinterpret_cast<float4*>(crow)     = v0;
        *reinterpret_cast<float4*>(crow + 4) = v1;
    }
}

// ---------------------------------------------------------------------------
// Per-row inverse L2 norms of q (cols 0..1023) and k (cols 1024..2047)
// ---------------------------------------------------------------------------
__global__ void rownorm_kernel()
{
    __shared__ float sqs[8], sks[8];
    const int r = blockIdx.x;
    const float* base = g_qkv + (size_t)r * N3D;

    float sq = 0.f, sk = 0.f;
    for (int d = threadIdx.x; d < DMODEL; d += 256) {
        float qv = base[d];
        float kv = base[DMODEL + d];
        sq += qv * qv;
        sk += kv * kv;
    }
    #pragma unroll
    for (int o = 16; o > 0; o >>= 1) {
        sq += __shfl_down_sync(0xffffffffu, sq, o);
        sk += __shfl_down_sync(0xffffffffu, sk, o);
    }
    const int w = threadIdx.x >> 5, l = threadIdx.x & 31;
    if (l == 0) { sqs[w] = sq; sks[w] = sk; }
    __syncthreads();
    if (threadIdx.x == 0) {
        float a = 0.f, b = 0.f;
        #pragma unroll
        for (int i = 0; i < 8; ++i) { a += sqs[i]; b += sks[i]; }
        g_invq[r] = rsqrtf(a);
        g_invk[r] = rsqrtf(b);
    }
}

// ---------------------------------------------------------------------------
// Pool stage 1: per-(T-chunk) partial kv[b,d] = sum_{t in chunk} khat * v
// grid (BATCH*DMODEL/256, TCHUNKS) — deterministic (no atomics)
// ---------------------------------------------------------------------------
__global__ void kvpool_partial_kernel()
{
    const int gi = blockIdx.x * 256 + threadIdx.x;   // 0..4095
    const int b  = gi >> 10;
    const int d  = gi & (DMODEL - 1);
    const int t0 = blockIdx.y * TPER;

    const int row0 = b * SEQT + t0;
    const float* p = g_qkv + (size_t)row0 * N3D + d;

    float acc = 0.f;
    #pragma unroll 4
    for (int t = 0; t < TPER; ++t) {
        float ik = g_invk[row0 + t];
        acc += (p[DMODEL] * ik) * p[2 * DMODEL];
        p += N3D;
    }
    g_kvpart[blockIdx.y * (BATCH * DMODEL) + gi] = acc;
}

// Pool stage 2: reduce the TCHUNKS partials
__global__ void kvpool_reduce_kernel()
{
    const int gi = blockIdx.x * 256 + threadIdx.x;
    float s = 0.f;
    #pragma unroll
    for (int c = 0; c < TCHUNKS; ++c)
        s += g_kvpart[c * (BATCH * DMODEL) + gi];
    g_kv[gi] = s;
}

// ---------------------------------------------------------------------------
// Launch
// ---------------------------------------------------------------------------
extern "C" void kernel_launch(void* const* d_in, const int* in_sizes, int n_in,
                              void* d_out, int out_size)
{
    const float* x    = (const float*)d_in[0];
    const float* Wqkv = (const float*)d_in[1];
    const float* bqkv = (const float*)d_in[2];
    const float* Wout = (const float*)d_in[3];
    const float* bout = (const float*)d_in[4];
    float* out = (float*)d_out;

    float *qkv, *invq, *kv;
    cudaGetSymbolAddress((void**)&qkv,  g_qkv);
    cudaGetSymbolAddress((void**)&invq, g_invq);
    cudaGetSymbolAddress((void**)&kv,   g_kv);

    // GEMM1: qkv = x @ Wqkv + bqkv
    sgemm_kernel<false><<<dim3(N3D / 128, MROWS / 128), 256>>>(
        x, DMODEL, Wqkv, N3D, bqkv, qkv, N3D, DMODEL, nullptr, nullptr);

    // Row inverse norms for q and k
    rownorm_kernel<<<MROWS, 256>>>();

    // kv pool (deterministic 2-stage)
    kvpool_partial_kernel<<<dim3(BATCH * DMODEL / 256, TCHUNKS), 256>>>();
    kvpool_reduce_kernel<<<BATCH * DMODEL / 256, 256>>>();

    // GEMM2: out = (qhat * kv) @ Wout + bout  (scaling fused into A load)
    sgemm_kernel<true><<<dim3(DMODEL / 128, MROWS / 128), 256>>>(
        qkv, N3D, Wout, DMODEL, bout, out, DMODEL, DMODEL, invq, kv);
}